// round 15
// baseline (speedup 1.0000x reference)
#include <cuda_runtime.h>
#include <cuda_bf16.h>
#include <cstdint>

#define BB 2
#define HH 16
#define SS 2048
#define DKK 64
#define SCALE 0.125f   // 1/sqrt(64)
#define KP 192         // split-precision concat depth for QK

typedef unsigned int U32;
typedef unsigned long long ULL;

// ---------------------------------------------------------------------------
// helpers
// ---------------------------------------------------------------------------
__device__ __forceinline__ U32 smem_u32(const void* p) {
    U32 a;
    asm("{ .reg .u64 t; cvta.to.shared.u64 t, %1; cvt.u32.u64 %0, t; }" : "=r"(a) : "l"(p));
    return a;
}

__device__ __forceinline__ void ldsm_x4(U32* r, U32 addr) {
    asm volatile("ldmatrix.sync.aligned.m8n8.x4.shared.b16 {%0,%1,%2,%3}, [%4];"
                 : "=r"(r[0]), "=r"(r[1]), "=r"(r[2]), "=r"(r[3]) : "r"(addr));
}
__device__ __forceinline__ void ldsm_x4_t(U32* r, U32 addr) {
    asm volatile("ldmatrix.sync.aligned.m8n8.x4.trans.shared.b16 {%0,%1,%2,%3}, [%4];"
                 : "=r"(r[0]), "=r"(r[1]), "=r"(r[2]), "=r"(r[3]) : "r"(addr));
}

// D += A * B, m16n8k16, bf16 inputs, fp32 accum
__device__ __forceinline__ void mma16816(float* d, const U32* a, const U32* b) {
    asm volatile(
        "mma.sync.aligned.m16n8k16.row.col.f32.bf16.bf16.f32 "
        "{%0,%1,%2,%3}, {%4,%5,%6,%7}, {%8,%9}, {%0,%1,%2,%3};"
        : "+f"(d[0]), "+f"(d[1]), "+f"(d[2]), "+f"(d[3])
        : "r"(a[0]), "r"(a[1]), "r"(a[2]), "r"(a[3]), "r"(b[0]), "r"(b[1]));
}

// pack two fp32 -> bf16x2 (x0 in low half, x1 in high half)
__device__ __forceinline__ U32 packbf(float x0, float x1) {
    U32 r;
    asm("cvt.rn.bf16x2.f32 %0, %1, %2;" : "=r"(r) : "f"(x1), "f"(x0));
    return r;
}
__device__ __forceinline__ float bfhi(float x) {
    return __bfloat162float(__float2bfloat16(x));
}

// ---------------------------------------------------------------------------
// device scratch
// ---------------------------------------------------------------------------
__device__ float g_attn_scratch[(size_t)BB * HH * SS * SS];
__device__ __nv_bfloat16 g_qcat[(size_t)BB * HH * SS * KP];  // [hi | lo | hi]
__device__ __nv_bfloat16 g_kcat[(size_t)BB * HH * SS * KP];  // [hi | hi | lo]
__device__ __nv_bfloat16 g_vhi[(size_t)BB * HH * SS * DKK];
__device__ __nv_bfloat16 g_vlo[(size_t)BB * HH * SS * DKK];
__device__ U32    g_mbits[(size_t)BB * SS * (SS / 32)];          // bit-packed mask (1 MB)
__device__ float2 g_part[(size_t)BB * HH * SS * (SS / 128)];     // per-row per-ktile (max,sumexp)

// ============================================================================
// Prepass 0: bit-pack mask via warp ballot.
// ============================================================================
__global__ __launch_bounds__(256)
void packmask_kernel(const int* __restrict__ mask) {
    size_t idx = (size_t)blockIdx.x * 256 + threadIdx.x;    // over all B*S*S elems
    int v = mask[idx];
    U32 b = __ballot_sync(0xffffffffu, v != 0);
    if ((threadIdx.x & 31) == 0) g_mbits[idx >> 5] = b;
}

// ============================================================================
// Prepass A: split fp32 rows (64) into bf16 blocks, K'=192 concat layout.
// mode 0: [hi | lo | hi]  (Q)      mode 1: [hi | hi | lo]  (K)
// ============================================================================
__global__ __launch_bounds__(256)
void split_kernel(const float* __restrict__ src, __nv_bfloat16* __restrict__ dst, int mode) {
    int idx = blockIdx.x * blockDim.x + threadIdx.x;   // 0 .. 65536*4-1
    int row = idx >> 2;
    int c16 = idx & 3;
    if (row >= BB * HH * SS) return;

    const float4* s = (const float4*)(src + (size_t)row * DKK + c16 * 16);
    U32 hi[8], lo[8];
#pragma unroll
    for (int i = 0; i < 4; ++i) {
        float4 v = s[i];
        float f[4] = {v.x, v.y, v.z, v.w};
#pragma unroll
        for (int j = 0; j < 2; ++j) {
            float a = f[2 * j], b = f[2 * j + 1];
            float ah = bfhi(a), bh = bfhi(b);
            hi[i * 2 + j] = packbf(ah, bh);
            lo[i * 2 + j] = packbf(a - ah, b - bh);
        }
    }
    U32* o = (U32*)(dst + (size_t)row * KP);
    int base = c16 * 8;
#pragma unroll
    for (int i = 0; i < 8; ++i) {
        o[base + i]      = hi[i];
        o[32 + base + i] = (mode == 0) ? lo[i] : hi[i];
        o[64 + base + i] = (mode == 0) ? hi[i] : lo[i];
    }
}

// ============================================================================
// Prepass B: split V into bf16 hi/lo arrays.
// ============================================================================
__global__ __launch_bounds__(256)
void vsplit_kernel(const float* __restrict__ V,
                   __nv_bfloat16* __restrict__ vhi, __nv_bfloat16* __restrict__ vlo) {
    int idx = blockIdx.x * blockDim.x + threadIdx.x;    // over float4s
    float4 v = ((const float4*)V)[idx];
    float h0 = bfhi(v.x), h1 = bfhi(v.y), h2 = bfhi(v.z), h3 = bfhi(v.w);
    ULL hv = (ULL)packbf(h0, h1) | ((ULL)packbf(h2, h3) << 32);
    ULL lv = (ULL)packbf(v.x - h0, v.y - h1) | ((ULL)packbf(v.z - h2, v.w - h3) << 32);
    ((ULL*)vhi)[idx] = hv;
    ((ULL*)vlo)[idx] = lv;
}

// ============================================================================
// Kernel 1: QK^T via mma.sync bf16 split (K'=192). 128x128 tile per CTA,
// 8 warps in 4(m) x 2(n). Epilogue: bitmask + scale, write RAW masked scores,
// reduce per-row (max, sumexp) partials -> g_part.
// ============================================================================
#define QK_SA 200                 // padded smem row stride in bf16 (400B, odd x16B)
#define QK_SMEM (2 * 128 * QK_SA * 2)

__global__ __launch_bounds__(256, 2)
void qk_mma_kernel(float* __restrict__ attn) {
    extern __shared__ __nv_bfloat16 smqk[];
    __nv_bfloat16* As = smqk;                  // [128][QK_SA]
    __nv_bfloat16* Bs = smqk + 128 * QK_SA;

    const int bh = blockIdx.z, b = bh >> 4;
    const int q0 = blockIdx.y * 128, k0 = blockIdx.x * 128;
    const int tid = threadIdx.x, lane = tid & 31, w = tid >> 5;
    const int wm = w >> 1, wn = w & 1;

    const uint4* Ag = (const uint4*)(g_qcat + ((size_t)bh * SS + q0) * KP);
    const uint4* Bg = (const uint4*)(g_kcat + ((size_t)bh * SS + k0) * KP);

#pragma unroll
    for (int t = 0; t < 12; ++t) {
        int idx = tid + t * 256;          // 0..3071
        int row = idx / 24, c = idx % 24; // 24 uint4 per row (192 bf16)
        *(uint4*)&As[row * QK_SA + c * 8] = Ag[row * 24 + c];
        *(uint4*)&Bs[row * QK_SA + c * 8] = Bg[row * 24 + c];
    }
    __syncthreads();

    float acc[2][8][4];
#pragma unroll
    for (int mt = 0; mt < 2; ++mt)
#pragma unroll
        for (int nt = 0; nt < 8; ++nt)
#pragma unroll
            for (int i = 0; i < 4; ++i) acc[mt][nt][i] = 0.f;

    const U32 aB = smem_u32(As), bB = smem_u32(Bs);
    U32 aAddr[2], bAddr[4];
#pragma unroll
    for (int mt = 0; mt < 2; ++mt)
        aAddr[mt] = aB + (U32)((wm * 32 + mt * 16 + (lane & 15)) * (QK_SA * 2)
                               + (((lane >> 4) << 3) << 1));
#pragma unroll
    for (int p = 0; p < 4; ++p)
        bAddr[p] = bB + (U32)((wn * 64 + p * 16 + (lane & 7) + ((lane >> 4) << 3)) * (QK_SA * 2)
                              + ((((lane >> 3) & 1) << 3) << 1));

#pragma unroll
    for (int ks = 0; ks < 12; ++ks) {
        U32 af[2][4], bf[8][2];
#pragma unroll
        for (int mt = 0; mt < 2; ++mt) ldsm_x4(af[mt], aAddr[mt] + ks * 32);
#pragma unroll
        for (int p = 0; p < 4; ++p) {
            U32 rr[4];
            ldsm_x4(rr, bAddr[p] + ks * 32);
            bf[2 * p][0] = rr[0]; bf[2 * p][1] = rr[1];
            bf[2 * p + 1][0] = rr[2]; bf[2 * p + 1][1] = rr[3];
        }
#pragma unroll
        for (int mt = 0; mt < 2; ++mt)
#pragma unroll
            for (int nt = 0; nt < 8; ++nt)
                mma16816(acc[mt][nt], af[mt], bf[nt]);
    }

    // ---- epilogue: bitmask + scale, write raw scores, row-stat partials ----
    const int lr = lane >> 2, lc = (lane & 3) * 2;
    float2* overlay = (float2*)smqk;     // alias As region: [128 rows][2 wn]
    __syncthreads();                     // all warps done with As/Bs

#pragma unroll
    for (int mt = 0; mt < 2; ++mt) {
#pragma unroll
        for (int half = 0; half < 2; ++half) {
            int rl = wm * 32 + mt * 16 + lr + half * 8;
            int qrow = q0 + rl;
            ULL wbits = *(const ULL*)(g_mbits + ((size_t)b * SS + qrow) * (SS / 32)
                                      + ((U32)(k0 + wn * 64) >> 5));
            float* orow = attn + ((size_t)bh * SS + qrow) * SS + k0 + wn * 64 + lc;
            float mx = -3.4e38f;
#pragma unroll
            for (int nt = 0; nt < 8; ++nt) {
                int j = lc + nt * 8;
                float2 v;
                v.x = ((wbits >> j) & 1)       ? acc[mt][nt][half * 2 + 0] * SCALE : -1e9f;
                v.y = ((wbits >> (j + 1)) & 1) ? acc[mt][nt][half * 2 + 1] * SCALE : -1e9f;
                *(float2*)(orow + nt * 8) = v;
                acc[mt][nt][half * 2 + 0] = v.x;
                acc[mt][nt][half * 2 + 1] = v.y;
                mx = fmaxf(mx, fmaxf(v.x, v.y));
            }
            float se = 0.f;
#pragma unroll
            for (int nt = 0; nt < 8; ++nt)
                se += __expf(acc[mt][nt][half * 2 + 0] - mx)
                    + __expf(acc[mt][nt][half * 2 + 1] - mx);
            // butterfly reduce across the 4 lanes sharing this row
#pragma unroll
            for (int o = 1; o <= 2; o <<= 1) {
                float om = __shfl_xor_sync(0xffffffffu, mx, o);
                float os = __shfl_xor_sync(0xffffffffu, se, o);
                float nm = fmaxf(mx, om);
                se = se * __expf(mx - nm) + os * __expf(om - nm);
                mx = nm;
            }
            if ((lane & 3) == 0) overlay[rl * 2 + wn] = make_float2(mx, se);
        }
    }
    __syncthreads();
    if (tid < 128) {
        float2 a0 = overlay[tid * 2 + 0], a1 = overlay[tid * 2 + 1];
        float nm = fmaxf(a0.x, a1.x);
        float ns = a0.y * __expf(a0.x - nm) + a1.y * __expf(a1.x - nm);
        g_part[((size_t)bh * SS + q0 + tid) * (SS / 128) + blockIdx.x] = make_float2(nm, ns);
    }
}

// ============================================================================
// Kernel 2 (fused): softmax-normalize + O = W @ V. 128q x 64d tile per CTA.
// Reduces row stats from g_part, reads RAW scores, writes normalized weights,
// splits W to hi/lo bf16 in-kernel; V pre-split. 3 MMA passes.
// ============================================================================
#define PV_WS 72                   // padded smem stride bf16 (144B, odd x16B)
#define PV_SMEM ((2 * 128 + 2 * 64) * PV_WS * 2 + 256 * 4)

__global__ __launch_bounds__(256, 2)
void normpv_mma_kernel(float* __restrict__ attn,
                       const __nv_bfloat16* __restrict__ vhi,
                       const __nv_bfloat16* __restrict__ vlo,
                       float* __restrict__ O) {
    extern __shared__ __nv_bfloat16 smpv[];
    __nv_bfloat16* Whi = smpv;                      // [128][72]
    __nv_bfloat16* Wlo = Whi + 128 * PV_WS;
    __nv_bfloat16* Vhs = Wlo + 128 * PV_WS;         // [64][72]
    __nv_bfloat16* Vls = Vhs + 64 * PV_WS;
    float* sm_m  = (float*)(Vls + 64 * PV_WS);      // [128]
    float* sm_is = sm_m + 128;                      // [128]

    const int bh = blockIdx.y, q0 = blockIdx.x * 128;
    const int tid = threadIdx.x, lane = tid & 31, w = tid >> 5;
    const int wm = w >> 1, wn = w & 1;

    // ---- reduce per-row stats (deterministic sequential merge over 16 tiles)
    if (tid < 128) {
        const float2* pp = g_part + ((size_t)bh * SS + q0 + tid) * (SS / 128);
        float2 c = pp[0];
        float m = c.x, s = c.y;
#pragma unroll
        for (int i = 1; i < SS / 128; ++i) {
            float2 p = pp[i];
            float nm = fmaxf(m, p.x);
            s = s * __expf(m - nm) + p.y * __expf(p.x - nm);
            m = nm;
        }
        sm_m[tid] = m;
        sm_is[tid] = 1.0f / s;
    }
    __syncthreads();

    float acc[2][4][4];
#pragma unroll
    for (int mt = 0; mt < 2; ++mt)
#pragma unroll
        for (int nt = 0; nt < 4; ++nt)
#pragma unroll
            for (int i = 0; i < 4; ++i) acc[mt][nt][i] = 0.f;

    const U32 whiB = smem_u32(Whi), wloB = smem_u32(Wlo);
    const U32 vhiB = smem_u32(Vhs), vloB = smem_u32(Vls);
    U32 wAddrHi[2], wAddrLo[2], vAddrHi[2], vAddrLo[2];
#pragma unroll
    for (int mt = 0; mt < 2; ++mt) {
        U32 off = (U32)((wm * 32 + mt * 16 + (lane & 15)) * (PV_WS * 2)
                        + (((lane >> 4) << 3) << 1));
        wAddrHi[mt] = whiB + off;
        wAddrLo[mt] = wloB + off;
    }
#pragma unroll
    for (int p = 0; p < 2; ++p) {
        U32 off = (U32)(((lane & 7) + (((lane >> 3) & 1) << 3)) * (PV_WS * 2)
                        + ((wn * 32 + p * 16 + ((lane >> 4) << 3)) << 1));
        vAddrHi[p] = vhiB + off;
        vAddrLo[p] = vloB + off;
    }

    for (int kt = 0; kt < 32; ++kt) {
        // W: read raw scores, normalize, write weights out, split hi/lo to smem
#pragma unroll
        for (int t = 0; t < 8; ++t) {
            int idx = tid + t * 256;
            int row = idx >> 4, c4 = idx & 15;
            float* gp = attn + ((size_t)bh * SS + q0 + row) * SS + kt * 64 + c4 * 4;
            float4 rv = *(const float4*)gp;
            float m = sm_m[row], is = sm_is[row];
            float w0 = __expf(rv.x - m) * is;
            float w1 = __expf(rv.y - m) * is;
            float w2 = __expf(rv.z - m) * is;
            float w3 = __expf(rv.w - m) * is;
            *(float4*)gp = make_float4(w0, w1, w2, w3);   // attn_weights output
            float h0 = bfhi(w0), h1 = bfhi(w1), h2 = bfhi(w2), h3 = bfhi(w3);
            *(ULL*)&Whi[row * PV_WS + c4 * 4] =
                (ULL)packbf(h0, h1) | ((ULL)packbf(h2, h3) << 32);
            *(ULL*)&Wlo[row * PV_WS + c4 * 4] =
                (ULL)packbf(w0 - h0, w1 - h1) | ((ULL)packbf(w2 - h2, w3 - h3) << 32);
        }
        // V tiles 64x64 bf16 (pre-split)
#pragma unroll
        for (int t = 0; t < 2; ++t) {
            int idx = tid + t * 256;
            int row = idx >> 3, c = idx & 7;
            size_t g = ((size_t)bh * SS + kt * 64 + row) * DKK + c * 8;
            *(uint4*)&Vhs[row * PV_WS + c * 8] = *(const uint4*)(vhi + g);
            *(uint4*)&Vls[row * PV_WS + c * 8] = *(const uint4*)(vlo + g);
        }
        __syncthreads();

#pragma unroll
        for (int ks = 0; ks < 4; ++ks) {
            U32 ah[2][4], al[2][4], bh2[4][2], bl2[4][2];
#pragma unroll
            for (int mt = 0; mt < 2; ++mt) {
                ldsm_x4(ah[mt], wAddrHi[mt] + ks * 32);
                ldsm_x4(al[mt], wAddrLo[mt] + ks * 32);
            }
#pragma unroll
            for (int p = 0; p < 2; ++p) {
                U32 rr[4];
                ldsm_x4_t(rr, vAddrHi[p] + ks * 16 * (PV_WS * 2));
                bh2[2 * p][0] = rr[0]; bh2[2 * p][1] = rr[1];
                bh2[2 * p + 1][0] = rr[2]; bh2[2 * p + 1][1] = rr[3];
                ldsm_x4_t(rr, vAddrLo[p] + ks * 16 * (PV_WS * 2));
                bl2[2 * p][0] = rr[0]; bl2[2 * p][1] = rr[1];
                bl2[2 * p + 1][0] = rr[2]; bl2[2 * p + 1][1] = rr[3];
            }
#pragma unroll
            for (int mt = 0; mt < 2; ++mt)
#pragma unroll
                for (int nt = 0; nt < 4; ++nt)
                    mma16816(acc[mt][nt], ah[mt], bh2[nt]);
#pragma unroll
            for (int mt = 0; mt < 2; ++mt)
#pragma unroll
                for (int nt = 0; nt < 4; ++nt)
                    mma16816(acc[mt][nt], al[mt], bh2[nt]);
#pragma unroll
            for (int mt = 0; mt < 2; ++mt)
#pragma unroll
                for (int nt = 0; nt < 4; ++nt)
                    mma16816(acc[mt][nt], ah[mt], bl2[nt]);
        }
        __syncthreads();
    }

    const int lr = lane >> 2, lc = (lane & 3) * 2;
#pragma unroll
    for (int mt = 0; mt < 2; ++mt) {
#pragma unroll
        for (int half = 0; half < 2; ++half) {
            int qrow = q0 + wm * 32 + mt * 16 + lr + half * 8;
            float* orow = O + ((size_t)bh * SS + qrow) * DKK + wn * 32 + lc;
#pragma unroll
            for (int nt = 0; nt < 4; ++nt) {
                float2 v;
                v.x = acc[mt][nt][half * 2 + 0];
                v.y = acc[mt][nt][half * 2 + 1];
                *(float2*)(orow + nt * 8) = v;
            }
        }
    }
}

// ============================================================================
// Launch
// ============================================================================
extern "C" void kernel_launch(void* const* d_in, const int* in_sizes, int n_in,
                              void* d_out, int out_size) {
    const float* Q    = (const float*)d_in[0];
    const float* K    = (const float*)d_in[1];
    const float* V    = (const float*)d_in[2];
    const int*   mask = (const int*)d_in[3];

    float* out = (float*)d_out;
    const long long O_ELEMS = (long long)BB * HH * SS * DKK;
    const long long A_ELEMS = (long long)BB * HH * SS * (long long)SS;

    float* Optr = out;
    float* attn;
    if ((long long)out_size >= O_ELEMS + A_ELEMS) {
        attn = out + O_ELEMS;
    } else {
        void* sp = nullptr;
        cudaGetSymbolAddress(&sp, g_attn_scratch);
        attn = (float*)sp;
    }

    __nv_bfloat16 *qcat, *kcat, *vhi, *vlo;
    { void* p; cudaGetSymbolAddress(&p, g_qcat); qcat = (__nv_bfloat16*)p; }
    { void* p; cudaGetSymbolAddress(&p, g_kcat); kcat = (__nv_bfloat16*)p; }
    { void* p; cudaGetSymbolAddress(&p, g_vhi);  vhi  = (__nv_bfloat16*)p; }
    { void* p; cudaGetSymbolAddress(&p, g_vlo);  vlo  = (__nv_bfloat16*)p; }

    cudaFuncSetAttribute(qk_mma_kernel, cudaFuncAttributeMaxDynamicSharedMemorySize, QK_SMEM);
    cudaFuncSetAttribute(normpv_mma_kernel, cudaFuncAttributeMaxDynamicSharedMemorySize, PV_SMEM);

    packmask_kernel<<<(unsigned)((size_t)BB * SS * SS / 256), 256>>>(mask);

    const int nthr = BB * HH * SS * 4;
    split_kernel<<<(nthr + 255) / 256, 256>>>(Q, qcat, 0);
    split_kernel<<<(nthr + 255) / 256, 256>>>(K, kcat, 1);
    vsplit_kernel<<<(BB * HH * SS * DKK / 4 + 255) / 256, 256>>>(V, vhi, vlo);

    dim3 g1(SS / 128, SS / 128, BB * HH);
    qk_mma_kernel<<<g1, 256, QK_SMEM>>>(attn);

    dim3 g3(SS / 128, BB * HH);
    normpv_mma_kernel<<<g3, 256, PV_SMEM>>>(attn, vhi, vlo, Optr);
}